// round 1
// baseline (speedup 1.0000x reference)
#include <cuda_runtime.h>
#include <math.h>

#define NROWS 500000
#define DDIM  256
#define BSEG  16384

// Scratch (device globals -- no allocation allowed)
__device__ float g_local[BSEG * DDIM];    // segment_sum(x*mask)          [B,256]
__device__ float g_L1[BSEG * DDIM];       // local_rep@W1 + b1 + b2       [B,256]
__device__ float g_att[NROWS];            // per-row attention scalar     [N]
__device__ float g_global[BSEG * DDIM];   // segment_sum(x*att)           [B,256]

__device__ __forceinline__ int lower_bound_dev(const int* __restrict__ arr, int n, int val) {
    int lo = 0, hi = n;
    while (lo < hi) {
        int mid = (lo + hi) >> 1;
        if (arr[mid] < val) lo = mid + 1; else hi = mid;
    }
    return lo;
}

// ---------------------------------------------------------------------------
// Segment pooling: one block per segment (batch is sorted -> contiguous rows).
// WHICH==0: out = g_local, weight = mask (param)
// WHICH==1: out = g_global, weight = g_att
// ---------------------------------------------------------------------------
template <int WHICH>
__global__ void seg_pool_kernel(const float* __restrict__ x,
                                const int*   __restrict__ batch,
                                const float* __restrict__ maskw) {
    int b = blockIdx.x;
    __shared__ int sb[2];
    if (threadIdx.x < 2)
        sb[threadIdx.x] = lower_bound_dev(batch, NROWS, b + (int)threadIdx.x);
    __syncthreads();
    int s = sb[0], e = sb[1];
    int d = threadIdx.x;
    float acc = 0.f;
    for (int r = s; r < e; ++r) {
        float w = (WHICH == 0) ? __ldg(&maskw[r]) : g_att[r];
        acc += x[(size_t)r * DDIM + d] * w;
    }
    if (WHICH == 0) g_local[(size_t)b * DDIM + d] = acc;
    else            g_global[(size_t)b * DDIM + d] = acc;
}

// ---------------------------------------------------------------------------
// SGEMM: 64-row x 256-col block tile, BK=8, 256 threads, 8x8 per thread.
// MODE 0: A = g_local,  B = W1,  out = g_L1 (+ b1 + b2)        K=256
// MODE 1: A = x (ext),  B = W2,  epilogue: att = sum_d w3[d]*sigmoid(c + g_L1[batch[row]][d])
//         warp-reduced (one warp owns a full output row) -> g_att            K=256
// MODE 2: A = concat(g_local, g_global), B = W4, out = d_out (+ b4)          K=512
// ---------------------------------------------------------------------------
template <int MODE, int KDIM>
__global__ void sgemm_kernel(const float* __restrict__ Aext,
                             const float* __restrict__ Bm,
                             const float* __restrict__ bias1,
                             const float* __restrict__ bias2,
                             const int*   __restrict__ batch,
                             const float* __restrict__ w3,
                             float*       __restrict__ outext,
                             int Mrows) {
    __shared__ __align__(16) float As[8 * 68];   // padded stride 68: conflict-free, 16B-aligned
    __shared__ __align__(16) float Bs[8 * 256];

    const int tid = threadIdx.x;
    const int tx = tid & 31;        // 32 col-groups
    const int ty = tid >> 5;        // 8 row-groups (ty also = warp id)
    const int row0 = blockIdx.x * 64;

    float c[8][8];
#pragma unroll
    for (int i = 0; i < 8; ++i)
#pragma unroll
        for (int j = 0; j < 8; ++j) c[i][j] = 0.f;

    const int ar = tid >> 2;            // 0..63 : A row within tile
    const int ak = (tid & 3) * 2;       // 0,2,4,6 : A k-offset (float2)

    for (int kt = 0; kt < KDIM / 8; ++kt) {
        const int k0 = kt * 8;
        // ---- A tile load (64 x 8), transposed into As[k][row]
        {
            int grow = row0 + ar;
            float2 v = make_float2(0.f, 0.f);
            if (grow < Mrows) {
                int kg = k0 + ak;
                const float* Ap;
                if (MODE == 2) {
                    Ap = (kg < 256) ? (g_local  + (size_t)grow * 256 + kg)
                                    : (g_global + (size_t)grow * 256 + (kg - 256));
                } else if (MODE == 0) {
                    Ap = g_local + (size_t)grow * 256 + kg;
                } else {
                    Ap = Aext + (size_t)grow * 256 + kg;
                }
                v = *reinterpret_cast<const float2*>(Ap);
            }
            As[ak * 68 + ar]       = v.x;
            As[(ak + 1) * 68 + ar] = v.y;
        }
        // ---- B tile load (8 x 256): row ty, two float4 per thread
        {
            const float4* Bp = reinterpret_cast<const float4*>(Bm + (size_t)(k0 + ty) * 256 + tx * 4);
            float4 b0 = Bp[0];
            float4 b1 = Bp[32];   // +128 floats
            *reinterpret_cast<float4*>(&Bs[ty * 256 + tx * 4])       = b0;
            *reinterpret_cast<float4*>(&Bs[ty * 256 + 128 + tx * 4]) = b1;
        }
        __syncthreads();
#pragma unroll
        for (int k = 0; k < 8; ++k) {
            float4 a0 = *reinterpret_cast<const float4*>(&As[k * 68 + ty * 8]);
            float4 a1 = *reinterpret_cast<const float4*>(&As[k * 68 + ty * 8 + 4]);
            float4 b0 = *reinterpret_cast<const float4*>(&Bs[k * 256 + tx * 4]);
            float4 b1 = *reinterpret_cast<const float4*>(&Bs[k * 256 + 128 + tx * 4]);
            float av[8] = {a0.x, a0.y, a0.z, a0.w, a1.x, a1.y, a1.z, a1.w};
            float bv[8] = {b0.x, b0.y, b0.z, b0.w, b1.x, b1.y, b1.z, b1.w};
#pragma unroll
            for (int i = 0; i < 8; ++i)
#pragma unroll
                for (int j = 0; j < 8; ++j)
                    c[i][j] += av[i] * bv[j];
        }
        __syncthreads();
    }

    // ---- Epilogues ----
    if (MODE == 0 || MODE == 2) {
        // thread's columns: tx*4 + j (j<4) and 128 + tx*4 + (j-4)
        const int c0 = tx * 4;
        const int c1 = 128 + tx * 4;
        float add0[4], add1[4];
#pragma unroll
        for (int j = 0; j < 4; ++j) {
            add0[j] = bias1[c0 + j] + (MODE == 0 ? bias2[c0 + j] : 0.f);
            add1[j] = bias1[c1 + j] + (MODE == 0 ? bias2[c1 + j] : 0.f);
        }
#pragma unroll
        for (int i = 0; i < 8; ++i) {
            int grow = row0 + ty * 8 + i;
            if (grow >= Mrows) continue;
            float* dst = (MODE == 0) ? (g_L1 + (size_t)grow * 256) : (outext + (size_t)grow * 256);
            float4 o0, o1;
            o0.x = c[i][0] + add0[0]; o0.y = c[i][1] + add0[1];
            o0.z = c[i][2] + add0[2]; o0.w = c[i][3] + add0[3];
            o1.x = c[i][4] + add1[0]; o1.y = c[i][5] + add1[1];
            o1.z = c[i][6] + add1[2]; o1.w = c[i][7] + add1[3];
            *reinterpret_cast<float4*>(dst + c0) = o0;
            *reinterpret_cast<float4*>(dst + c1) = o1;
        }
    } else {
        // MODE 1: attention epilogue. One warp (ty) owns rows ty*8..ty*8+7 across
        // all 256 columns -> warp shuffle reduce gives the full w3-weighted row sum.
        const int c0 = tx * 4;
        const int c1 = 128 + tx * 4;
        float w3a[4], w3b[4];
#pragma unroll
        for (int j = 0; j < 4; ++j) { w3a[j] = __ldg(&w3[c0 + j]); w3b[j] = __ldg(&w3[c1 + j]); }
#pragma unroll
        for (int i = 0; i < 8; ++i) {
            int grow = row0 + ty * 8 + i;
            if (grow >= Mrows) continue;           // uniform per warp (same ty)
            int seg = __ldg(&batch[grow]);
            const float* Lr = g_L1 + (size_t)seg * 256;
            float partial = 0.f;
#pragma unroll
            for (int j = 0; j < 4; ++j) {
                float h = c[i][j] + Lr[c0 + j];
                partial += w3a[j] * (1.f / (1.f + __expf(-h)));
            }
#pragma unroll
            for (int j = 4; j < 8; ++j) {
                float h = c[i][j] + Lr[c1 + (j - 4)];
                partial += w3b[j - 4] * (1.f / (1.f + __expf(-h)));
            }
#pragma unroll
            for (int off = 16; off > 0; off >>= 1)
                partial += __shfl_xor_sync(0xffffffffu, partial, off);
            if (tx == 0) g_att[grow] = partial;
        }
    }
}

extern "C" void kernel_launch(void* const* d_in, const int* in_sizes, int n_in,
                              void* d_out, int out_size) {
    // Input order: x, batch, last_click_mask, [num_segments], W1, b1, W2, b2, w3, W4, b4
    const float* x    = (const float*)d_in[0];
    const int*   batch= (const int*)  d_in[1];
    const float* mask = (const float*)d_in[2];
    int o = (n_in >= 11 && in_sizes[3] == 1) ? 4 : 3;
    const float* W1 = (const float*)d_in[o + 0];
    const float* b1 = (const float*)d_in[o + 1];
    const float* W2 = (const float*)d_in[o + 2];
    const float* b2 = (const float*)d_in[o + 3];
    const float* w3 = (const float*)d_in[o + 4];
    const float* W4 = (const float*)d_in[o + 5];
    const float* b4 = (const float*)d_in[o + 6];
    float* out = (float*)d_out;

    // 1) local_rep = segment_sum(x * mask)
    seg_pool_kernel<0><<<BSEG, 256>>>(x, batch, mask);
    // 2) g_L1 = local_rep @ W1 + b1 + b2   (B rows only -- not N!)
    sgemm_kernel<0, 256><<<BSEG / 64, 256>>>(nullptr, W1, b1, b2, nullptr, nullptr, nullptr, BSEG);
    // 3) att[i] = sum_d w3[d] * sigmoid( (x@W2)[i,d] + g_L1[batch[i],d] )
    sgemm_kernel<1, 256><<<(NROWS + 63) / 64, 256>>>(x, W2, nullptr, nullptr, batch, w3, nullptr, NROWS);
    // 4) global_rep = segment_sum(x * att)
    seg_pool_kernel<1><<<BSEG, 256>>>(x, batch, nullptr);
    // 5) out = [local_rep, global_rep] @ W4 + b4
    sgemm_kernel<2, 512><<<BSEG / 64, 256>>>(nullptr, W4, b4, nullptr, nullptr, nullptr, out, BSEG);
}

// round 3
// speedup vs baseline: 1.2940x; 1.2940x over previous
#include <cuda_runtime.h>
#include <cuda_bf16.h>
#include <math.h>
#include <cstdint>

#define NROWS 500000
#define DDIM  256
#define BSEG  16384

// ---------------- scratch (device globals; no allocs allowed) ----------------
__device__ float g_local[BSEG * DDIM];
__device__ float g_L1[BSEG * DDIM];
__device__ float g_att[NROWS];
__device__ float g_global[BSEG * DDIM];
__device__ float g_W2t[DDIM * DDIM];     // W2 pre-rounded to tf32

// ---------------- small helpers ----------------
__device__ __forceinline__ uint32_t smem_to_u32(const void* smem_ptr) {
    uint32_t addr;
    asm("{ .reg .u64 tmp; cvta.to.shared.u64 tmp, %1; cvt.u32.u64 %0, tmp; }"
        : "=r"(addr) : "l"(smem_ptr));
    return addr;
}
__device__ __forceinline__ uint32_t cvt_tf32(float f) {
    uint32_t u;
    asm("cvt.rna.tf32.f32 %0, %1;" : "=r"(u) : "f"(f));
    return u;
}
__device__ __forceinline__ void cp_async16(uint32_t dst, const void* src, bool pred) {
    int sz = pred ? 16 : 0;
    asm volatile("cp.async.cg.shared.global [%0], [%1], 16, %2;\n"
                 :: "r"(dst), "l"(src), "r"(sz));
}
#define CP_COMMIT() asm volatile("cp.async.commit_group;\n" ::)
#define CP_WAIT1()  asm volatile("cp.async.wait_group 1;\n" ::)
#define CP_WAIT0()  asm volatile("cp.async.wait_group 0;\n" ::)

__device__ __forceinline__ void mma_tf32(float* d, const uint32_t* a, uint32_t b0, uint32_t b1) {
    asm volatile("mma.sync.aligned.m16n8k8.row.col.f32.tf32.tf32.f32 "
                 "{%0,%1,%2,%3}, {%4,%5,%6,%7}, {%8,%9}, {%0,%1,%2,%3};"
                 : "+f"(d[0]), "+f"(d[1]), "+f"(d[2]), "+f"(d[3])
                 : "r"(a[0]), "r"(a[1]), "r"(a[2]), "r"(a[3]), "r"(b0), "r"(b1));
}

__device__ __forceinline__ int lower_bound_dev(const int* __restrict__ arr, int n, int val) {
    int lo = 0, hi = n;
    while (lo < hi) { int mid = (lo + hi) >> 1; if (arr[mid] < val) lo = mid + 1; else hi = mid; }
    return lo;
}

// ---------------------------------------------------------------------------
// Segment pooling (batch sorted -> contiguous). 4x unrolled for MLP.
// ---------------------------------------------------------------------------
template <int WHICH>
__global__ void seg_pool_kernel(const float* __restrict__ x,
                                const int*   __restrict__ batch,
                                const float* __restrict__ maskw) {
    int b = blockIdx.x;
    __shared__ int sb[2];
    if (threadIdx.x < 2)
        sb[threadIdx.x] = lower_bound_dev(batch, NROWS, b + (int)threadIdx.x);
    __syncthreads();
    int s = sb[0], e = sb[1];
    int d = threadIdx.x;
    float acc = 0.f;
    int r = s;
    for (; r + 3 < e; r += 4) {
        float w0, w1, w2, w3v;
        if (WHICH == 0) { w0 = __ldg(&maskw[r]); w1 = __ldg(&maskw[r+1]); w2 = __ldg(&maskw[r+2]); w3v = __ldg(&maskw[r+3]); }
        else            { w0 = g_att[r]; w1 = g_att[r+1]; w2 = g_att[r+2]; w3v = g_att[r+3]; }
        float x0 = x[(size_t)r * DDIM + d];
        float x1 = x[(size_t)(r+1) * DDIM + d];
        float x2 = x[(size_t)(r+2) * DDIM + d];
        float x3 = x[(size_t)(r+3) * DDIM + d];
        acc += x0 * w0 + x1 * w1 + x2 * w2 + x3 * w3v;
    }
    for (; r < e; ++r) {
        float w = (WHICH == 0) ? __ldg(&maskw[r]) : g_att[r];
        acc += x[(size_t)r * DDIM + d] * w;
    }
    if (WHICH == 0) g_local[(size_t)b * DDIM + d] = acc;
    else            g_global[(size_t)b * DDIM + d] = acc;
}

// ---------------------------------------------------------------------------
// Pre-round W2 to tf32 (keeps mainloop free of B-side cvt).
// ---------------------------------------------------------------------------
__global__ void pack_W2_tf32(const float* __restrict__ W2) {
    int i = blockIdx.x * 256 + threadIdx.x;
    g_W2t[i] = __uint_as_float(cvt_tf32(W2[i]));
}

// ---------------------------------------------------------------------------
// att kernel: mma.sync tf32 GEMM (BM=128, BN=256, BK=32, cp.async x2 buffer)
// + fused epilogue: att[r] = sum_c w3[c]*sigmoid((x@W2)[r,c] + L1[batch[r],c])
// TMEM-free; pure sm_80-feature-set tensor path.
// ---------------------------------------------------------------------------
#define AS_STRIDE 36
#define BS_STRIDE 260
#define AS_BUF (128 * AS_STRIDE)
#define BS_BUF (32 * BS_STRIDE)
#define ATT_SMEM_BYTES ((2 * AS_BUF + 2 * BS_BUF + 128) * 4)

__global__ void __launch_bounds__(256, 1)
att_mma_kernel(const float* __restrict__ x,
               const int*   __restrict__ batch,
               const float* __restrict__ w3) {
    extern __shared__ __align__(16) float smem[];
    float* As = smem;                        // [2][128][36]
    float* Bs = smem + 2 * AS_BUF;           // [2][32][260]
    float* att_s = Bs + 2 * BS_BUF;          // [128]

    const int tid = threadIdx.x;
    const int lane = tid & 31;
    const int wid = tid >> 5;
    const int wm = wid & 3;        // 4 row groups of 32
    const int wn = wid >> 2;       // 2 col groups of 128
    const long row0 = (long)blockIdx.x * 128;

    const uint32_t As_u = smem_to_u32(As);
    const uint32_t Bs_u = smem_to_u32(Bs);

    float acc[2][16][4];
#pragma unroll
    for (int mt = 0; mt < 2; ++mt)
#pragma unroll
        for (int nt = 0; nt < 16; ++nt)
#pragma unroll
            for (int q = 0; q < 4; ++q) acc[mt][nt][q] = 0.f;

    // tile loader: A 128x32 from x, B 32x256 from g_W2t
    auto load_tile = [&](int kt, int buf) {
#pragma unroll
        for (int i = 0; i < 4; ++i) {
            int idx = tid + i * 256;
            int r = idx >> 3, c4 = idx & 7;
            long gr = row0 + r;
            const float* src = x + gr * 256 + kt * 32 + c4 * 4;
            uint32_t dst = As_u + (uint32_t)(buf * AS_BUF + r * AS_STRIDE + c4 * 4) * 4;
            cp_async16(dst, src, gr < NROWS);
        }
#pragma unroll
        for (int i = 0; i < 8; ++i) {
            int idx = tid + i * 256;
            int k = idx >> 6, n4 = idx & 63;
            const float* src = g_W2t + (size_t)(kt * 32 + k) * 256 + n4 * 4;
            uint32_t dst = Bs_u + (uint32_t)(buf * BS_BUF + k * BS_STRIDE + n4 * 4) * 4;
            cp_async16(dst, src, true);
        }
    };

    load_tile(0, 0);
    CP_COMMIT();

    for (int kt = 0; kt < 8; ++kt) {
        if (kt < 7) { load_tile(kt + 1, (kt + 1) & 1); CP_COMMIT(); CP_WAIT1(); }
        else        { CP_WAIT0(); }
        __syncthreads();

        const float* Asb = As + (kt & 1) * AS_BUF;
        const float* Bsb = Bs + (kt & 1) * BS_BUF;
#pragma unroll
        for (int kk = 0; kk < 32; kk += 8) {
            uint32_t af[2][4];
#pragma unroll
            for (int mt = 0; mt < 2; ++mt) {
                int r = wm * 32 + mt * 16 + (lane >> 2);
                int c = kk + (lane & 3);
                af[mt][0] = cvt_tf32(Asb[r * AS_STRIDE + c]);
                af[mt][1] = cvt_tf32(Asb[(r + 8) * AS_STRIDE + c]);
                af[mt][2] = cvt_tf32(Asb[r * AS_STRIDE + c + 4]);
                af[mt][3] = cvt_tf32(Asb[(r + 8) * AS_STRIDE + c + 4]);
            }
#pragma unroll
            for (int nt = 0; nt < 16; ++nt) {
                int n = wn * 128 + nt * 8 + (lane >> 2);
                int k = kk + (lane & 3);
                uint32_t b0 = __float_as_uint(Bsb[k * BS_STRIDE + n]);
                uint32_t b1 = __float_as_uint(Bsb[(k + 4) * BS_STRIDE + n]);
                mma_tf32(acc[0][nt], af[0], b0, b1);
                mma_tf32(acc[1][nt], af[1], b0, b1);
            }
        }
        __syncthreads();
    }

    // ---- fused epilogue ----
    if (tid < 128) att_s[tid] = 0.f;
    __syncthreads();

#pragma unroll
    for (int mt = 0; mt < 2; ++mt) {
#pragma unroll
        for (int half = 0; half < 2; ++half) {
            int lr = wm * 32 + mt * 16 + (lane >> 2) + half * 8;
            long gr = row0 + lr;
            if (gr < NROWS) {
                int seg = __ldg(&batch[gr]);
                const float* L1r = g_L1 + (size_t)seg * 256;
                float p = 0.f;
#pragma unroll
                for (int nt = 0; nt < 16; ++nt) {
                    int c = wn * 128 + nt * 8 + (lane & 3) * 2;
                    float v0 = acc[mt][nt][half * 2 + 0] + __ldg(L1r + c);
                    float v1 = acc[mt][nt][half * 2 + 1] + __ldg(L1r + c + 1);
                    float s0 = __fdividef(1.f, 1.f + __expf(-v0));
                    float s1 = __fdividef(1.f, 1.f + __expf(-v1));
                    p += __ldg(&w3[c]) * s0 + __ldg(&w3[c + 1]) * s1;
                }
                atomicAdd(&att_s[lr], p);
            }
        }
    }
    __syncthreads();
    if (tid < 128 && row0 + tid < NROWS) g_att[row0 + tid] = att_s[tid];
}

// ---------------------------------------------------------------------------
// fp32 SGEMM (MODE 0: L1 buffer; MODE 2: final output)
// ---------------------------------------------------------------------------
template <int MODE, int KDIM>
__global__ void sgemm_kernel(const float* __restrict__ Bm,
                             const float* __restrict__ bias1,
                             const float* __restrict__ bias2,
                             float*       __restrict__ outext,
                             int Mrows) {
    __shared__ __align__(16) float As[8 * 68];
    __shared__ __align__(16) float Bsh[8 * 256];
    const int tid = threadIdx.x;
    const int tx = tid & 31;
    const int ty = tid >> 5;
    const int row0 = blockIdx.x * 64;
    float c[8][8];
#pragma unroll
    for (int i = 0; i < 8; ++i)
#pragma unroll
        for (int j = 0; j < 8; ++j) c[i][j] = 0.f;
    const int ar = tid >> 2;
    const int ak = (tid & 3) * 2;
    for (int kt = 0; kt < KDIM / 8; ++kt) {
        const int k0 = kt * 8;
        {
            int grow = row0 + ar;
            float2 v = make_float2(0.f, 0.f);
            if (grow < Mrows) {
                int kg = k0 + ak;
                const float* Ap;
                if (MODE == 2) Ap = (kg < 256) ? (g_local + (size_t)grow * 256 + kg)
                                               : (g_global + (size_t)grow * 256 + (kg - 256));
                else           Ap = g_local + (size_t)grow * 256 + kg;
                v = *reinterpret_cast<const float2*>(Ap);
            }
            As[ak * 68 + ar] = v.x;
            As[(ak + 1) * 68 + ar] = v.y;
        }
        {
            const float4* Bp = reinterpret_cast<const float4*>(Bm + (size_t)(k0 + ty) * 256 + tx * 4);
            float4 b0 = Bp[0];
            float4 b1 = Bp[32];
            *reinterpret_cast<float4*>(&Bsh[ty * 256 + tx * 4]) = b0;
            *reinterpret_cast<float4*>(&Bsh[ty * 256 + 128 + tx * 4]) = b1;
        }
        __syncthreads();
#pragma unroll
        for (int k = 0; k < 8; ++k) {
            float4 a0 = *reinterpret_cast<const float4*>(&As[k * 68 + ty * 8]);
            float4 a1 = *reinterpret_cast<const float4*>(&As[k * 68 + ty * 8 + 4]);
            float4 b0 = *reinterpret_cast<const float4*>(&Bsh[k * 256 + tx * 4]);
            float4 b1 = *reinterpret_cast<const float4*>(&Bsh[k * 256 + 128 + tx * 4]);
            float av[8] = {a0.x, a0.y, a0.z, a0.w, a1.x, a1.y, a1.z, a1.w};
            float bv[8] = {b0.x, b0.y, b0.z, b0.w, b1.x, b1.y, b1.z, b1.w};
#pragma unroll
            for (int i = 0; i < 8; ++i)
#pragma unroll
                for (int j = 0; j < 8; ++j) c[i][j] += av[i] * bv[j];
        }
        __syncthreads();
    }
    const int c0 = tx * 4;
    const int c1 = 128 + tx * 4;
    float add0[4], add1[4];
#pragma unroll
    for (int j = 0; j < 4; ++j) {
        add0[j] = bias1[c0 + j] + (MODE == 0 ? bias2[c0 + j] : 0.f);
        add1[j] = bias1[c1 + j] + (MODE == 0 ? bias2[c1 + j] : 0.f);
    }
#pragma unroll
    for (int i = 0; i < 8; ++i) {
        int grow = row0 + ty * 8 + i;
        if (grow >= Mrows) continue;
        float* dst = (MODE == 0) ? (g_L1 + (size_t)grow * 256) : (outext + (size_t)grow * 256);
        float4 o0, o1;
        o0.x = c[i][0] + add0[0]; o0.y = c[i][1] + add0[1];
        o0.z = c[i][2] + add0[2]; o0.w = c[i][3] + add0[3];
        o1.x = c[i][4] + add1[0]; o1.y = c[i][5] + add1[1];
        o1.z = c[i][6] + add1[2]; o1.w = c[i][7] + add1[3];
        *reinterpret_cast<float4*>(dst + c0) = o0;
        *reinterpret_cast<float4*>(dst + c1) = o1;
    }
}

extern "C" void kernel_launch(void* const* d_in, const int* in_sizes, int n_in,
                              void* d_out, int out_size) {
    const float* x     = (const float*)d_in[0];
    const int*   batch = (const int*)  d_in[1];
    const float* mask  = (const float*)d_in[2];
    int o = (n_in >= 11 && in_sizes[3] == 1) ? 4 : 3;
    const float* W1 = (const float*)d_in[o + 0];
    const float* b1 = (const float*)d_in[o + 1];
    const float* W2 = (const float*)d_in[o + 2];
    const float* b2 = (const float*)d_in[o + 3];
    const float* w3 = (const float*)d_in[o + 4];
    const float* W4 = (const float*)d_in[o + 5];
    const float* b4 = (const float*)d_in[o + 6];
    float* out = (float*)d_out;

    cudaFuncSetAttribute(att_mma_kernel, cudaFuncAttributeMaxDynamicSharedMemorySize,
                         ATT_SMEM_BYTES);

    // 0) round W2 to tf32 once
    pack_W2_tf32<<<256, 256>>>(W2);
    // 1) local_rep = segment_sum(x * mask)
    seg_pool_kernel<0><<<BSEG, 256>>>(x, batch, mask);
    // 2) g_L1 = local_rep @ W1 + b1 + b2   (B rows only)
    sgemm_kernel<0, 256><<<BSEG / 64, 256>>>(W1, b1, b2, nullptr, BSEG);
    // 3) att via mma.sync tf32 GEMM + fused sigmoid/w3 epilogue
    att_mma_kernel<<<(NROWS + 127) / 128, 256, ATT_SMEM_BYTES>>>(x, batch, w3);
    // 4) global_rep = segment_sum(x * att)
    seg_pool_kernel<1><<<BSEG, 256>>>(x, batch, nullptr);
    // 5) out = [local_rep, global_rep] @ W4 + b4
    sgemm_kernel<2, 512><<<BSEG / 64, 256>>>(W4, b4, nullptr, out, BSEG);
}